// round 4
// baseline (speedup 1.0000x reference)
#include <cuda_runtime.h>
#include <cuda_fp16.h>
#include <cstdint>

// ---------------------------------------------------------------------------
// GATv2 collapsed:
//   out[e] = leaky_relu( P[src[e]] + Q[dst[e]] ) . w2 + b2
//   PQ = node_feat @ Wc + bc,  Wc = [W_node; b_node] @ W_a1 (biases folded)
// Layer loop idempotent; edge-hidden path dead. PQ stored fp16 (L2 traffic /2).
// ---------------------------------------------------------------------------

#define CH 128
#define MAX_NODES 10240
#define MAX_K 128

__device__ __half g_PQh[MAX_NODES * 2 * CH];   // per node: [P(128) | Q(128)] fp16
__device__ float  g_Wc[MAX_K * 2 * CH];        // combined weight [K, 256]
__device__ float  g_bc[2 * CH];                // combined bias   [256]

// packed fp32x2 FMA (Blackwell)
__device__ __forceinline__ void fma_f32x2(unsigned long long& d,
                                          unsigned long long a,
                                          unsigned long long b,
                                          unsigned long long c) {
    asm("fma.rn.f32x2 %0, %1, %2, %3;" : "=l"(d) : "l"(a), "l"(b), "l"(c));
}
__device__ __forceinline__ unsigned long long pack_f32x2(float lo, float hi) {
    unsigned long long r;
    asm("mov.b64 %0, {%1, %2};" : "=l"(r) : "r"(__float_as_uint(lo)), "r"(__float_as_uint(hi)));
    return r;
}
__device__ __forceinline__ void unpack_f32x2(unsigned long long v, float& lo, float& hi) {
    unsigned int a, b;
    asm("mov.b64 {%0, %1}, %2;" : "=r"(a), "=r"(b) : "l"(v));
    lo = __uint_as_float(a);
    hi = __uint_as_float(b);
}

// ---------------------------------------------------------------------------
// Kernel 1: Wc[119x256] = [W_node; b_node] @ W_a1-half.
// 32 blocks (4 row-tiles x 8 col-tiles of 32 cols), 256 thr, 2x2 micro-tile.
// All inner LDS are warp-broadcast or stride-1: conflict-free.
// ---------------------------------------------------------------------------
__global__ __launch_bounds__(256) void build_wc_kernel(
    const float* __restrict__ W_node,   // [K,128]
    const float* __restrict__ b_node,   // [128]
    const float* __restrict__ W_a1,     // [256,128]
    const float* __restrict__ b_a1,     // [128]
    int K) {
    __shared__ __align__(16) float As[32][128];   // 16 KB
    __shared__ __align__(16) float Bs[128][32];   // 16 KB

    int tid   = threadIdx.x;
    int kbase = blockIdx.x * 32;
    int jbase = blockIdx.y * 32;          // 0..224, never crosses the 128 split
    int half  = jbase >> 7;
    int jloc  = jbase & (CH - 1);

    // A tile: 32 rows x 128 floats = 1024 float4, 4 per thread (coalesced).
#pragma unroll
    for (int i = 0; i < 4; i++) {
        int id = tid + i * 256;
        int r  = id >> 5;
        int c4 = id & 31;
        int k  = kbase + r;
        float4 v = make_float4(0.f, 0.f, 0.f, 0.f);
        if (k < K)       v = ((const float4*)(W_node + (size_t)k * CH))[c4];
        else if (k == K) v = ((const float4*)b_node)[c4];
        *(float4*)&As[r][c4 * 4] = v;
    }
    // B tile: Bs[c][j] = W_a1[half*128 + c][jloc + j], 128x32 floats = 1024 float4.
#pragma unroll
    for (int i = 0; i < 4; i++) {
        int id = tid + i * 256;
        int c  = id >> 3;                 // 0..127
        int j4 = id & 7;                  // float4 within 32-col slice
        float4 v = ((const float4*)(W_a1 + (size_t)(half * CH + c) * CH + jloc))[j4];
        *(float4*)&Bs[c][j4 * 4] = v;
    }
    __syncthreads();

    int c2 = tid & 15;                    // cols c2, c2+16
    int r2 = tid >> 4;                    // rows r2, r2+16
    float acc[2][2] = {};
#pragma unroll 8
    for (int k = 0; k < 128; k++) {
        float b0 = Bs[k][c2];
        float b1 = Bs[k][c2 + 16];
        float a0 = As[r2][k];
        float a1 = As[r2 + 16][k];
        acc[0][0] = fmaf(a0, b0, acc[0][0]);
        acc[0][1] = fmaf(a0, b1, acc[0][1]);
        acc[1][0] = fmaf(a1, b0, acc[1][0]);
        acc[1][1] = fmaf(a1, b1, acc[1][1]);
    }

#pragma unroll
    for (int i = 0; i < 2; i++) {
        int k = kbase + r2 + 16 * i;
#pragma unroll
        for (int j = 0; j < 2; j++) {
            int jj = jbase + c2 + 16 * j;
            if (k < K) {
                g_Wc[(size_t)k * (2 * CH) + jj] = acc[i][j];
            } else if (k == K) {
                g_bc[jj] = acc[i][j] + (half ? b_a1[jj - CH] : 0.f);
            }
        }
    }
}

// ---------------------------------------------------------------------------
// Kernel 2: SGEMM  PQ[M,256] = node_feat[M,K] @ g_Wc[K,256] + g_bc  -> fp16
// 128x128 tile, BK=8, 8x8 per thread via fp32x2 packed FMA, 256 threads,
// register double-buffering to hide global latency across k-steps.
// ---------------------------------------------------------------------------
__global__ __launch_bounds__(256) void sgemm_bias_kernel(
    const float* __restrict__ A, int M, int K) {
    const int N = 2 * CH;
    __shared__ __align__(16) float As[8][128];
    __shared__ __align__(16) float Bs[8][128];

    int brow = blockIdx.x * 128;
    int bcol = blockIdx.y * 128;
    int tid  = threadIdx.x;
    int tr   = (tid >> 4) * 8;
    int tc   = (tid & 15) * 8;

    unsigned long long acc64[8][4];
#pragma unroll
    for (int i = 0; i < 8; i++)
#pragma unroll
        for (int j = 0; j < 4; j++) acc64[i][j] = 0ull;

    int aRow = tid >> 1;
    int aK   = (tid & 1) * 4;
    int bK   = tid >> 5;
    int bN   = (tid & 31) * 4;
    int m    = brow + aRow;

    // prologue: stage k0 = 0
    {
#pragma unroll
        for (int i = 0; i < 4; i++) {
            int k = aK + i;
            As[aK + i][aRow] = (m < M && k < K) ? A[(size_t)m * K + k] : 0.f;
        }
        float4 v = make_float4(0.f, 0.f, 0.f, 0.f);
        if (bK < K) v = *(const float4*)&g_Wc[bK * N + bcol + bN];
        *(float4*)&Bs[bK][bN] = v;
    }
    __syncthreads();

    for (int k0 = 0; k0 < K; k0 += 8) {
        // prefetch next tile into registers
        float  an[4];
        float4 bn = make_float4(0.f, 0.f, 0.f, 0.f);
        bool more = (k0 + 8 < K);
        if (more) {
#pragma unroll
            for (int i = 0; i < 4; i++) {
                int k = k0 + 8 + aK + i;
                an[i] = (m < M && k < K) ? A[(size_t)m * K + k] : 0.f;
            }
            int k = k0 + 8 + bK;
            if (k < K) bn = *(const float4*)&g_Wc[k * N + bcol + bN];
        }

#pragma unroll
        for (int kk = 0; kk < 8; kk++) {
            float a[8];
            *(float4*)&a[0] = *(const float4*)&As[kk][tr];
            *(float4*)&a[4] = *(const float4*)&As[kk][tr + 4];
            ulonglong2 t0 = *(const ulonglong2*)&Bs[kk][tc];
            ulonglong2 t1 = *(const ulonglong2*)&Bs[kk][tc + 4];
            unsigned long long b64[4] = {t0.x, t0.y, t1.x, t1.y};
#pragma unroll
            for (int i = 0; i < 8; i++) {
                unsigned long long aa = pack_f32x2(a[i], a[i]);
#pragma unroll
                for (int j = 0; j < 4; j++)
                    fma_f32x2(acc64[i][j], aa, b64[j], acc64[i][j]);
            }
        }
        __syncthreads();
        if (more) {
#pragma unroll
            for (int i = 0; i < 4; i++) As[aK + i][aRow] = an[i];
            *(float4*)&Bs[bK][bN] = bn;
        }
        __syncthreads();
    }

#pragma unroll
    for (int i = 0; i < 8; i++) {
        int mm = brow + tr + i;
        if (mm >= M) continue;
        __half2* orow = (__half2*)&g_PQh[(size_t)mm * N + bcol + tc];
#pragma unroll
        for (int j = 0; j < 4; j++) {
            int n = bcol + tc + 2 * j;
            float lo, hi;
            unpack_f32x2(acc64[i][j], lo, hi);
            lo += g_bc[n];
            hi += g_bc[n + 1];
            orow[j] = __floats2half2_rn(lo, hi);
        }
    }
}

// ---------------------------------------------------------------------------
// Kernel 3: per-edge. 8 lanes per edge (4 edges/warp); lane owns 16 channels
// via 2 uint4 per operand half -> 4 independent LDG.128 (MLP 4).
// half2 add+leaky, fp32 dot, 3-step shuffle reduce over 8 lanes.
// ---------------------------------------------------------------------------
__global__ __launch_bounds__(256) void edge_kernel(
    const int* __restrict__ src, const int* __restrict__ dst,
    const float* __restrict__ W_a2,   // [128]
    const float* __restrict__ b_a2,   // [1]
    float* __restrict__ out, int E) {
    int gwarp = (blockIdx.x * blockDim.x + threadIdx.x) >> 5;
    int lane  = threadIdx.x & 31;
    int sub   = lane & 7;             // 0..7: channels [16*sub, 16*sub+16)
    int e     = gwarp * 4 + (lane >> 3);

    bool valid = (e < E);
    int ec = valid ? e : 0;
    int s = src[ec];
    int d = dst[ec];

    const uint4* PQ = (const uint4*)g_PQh;        // 32 uint4 per node row
    const uint4* prow = PQ + (size_t)s * 32;
    const uint4* qrow = PQ + (size_t)d * 32 + 16;
    uint4 pv0 = prow[sub * 2];
    uint4 pv1 = prow[sub * 2 + 1];
    uint4 qv0 = qrow[sub * 2];
    uint4 qv1 = qrow[sub * 2 + 1];

    const float4* w4 = (const float4*)W_a2 + sub * 4;
    float4 w0 = w4[0], w1 = w4[1], w2 = w4[2], w3 = w4[3];
    float wv[16] = {w0.x, w0.y, w0.z, w0.w, w1.x, w1.y, w1.z, w1.w,
                    w2.x, w2.y, w2.z, w2.w, w3.x, w3.y, w3.z, w3.w};

    const __half2* ph0 = (const __half2*)&pv0;
    const __half2* ph1 = (const __half2*)&pv1;
    const __half2* qh0 = (const __half2*)&qv0;
    const __half2* qh1 = (const __half2*)&qv1;

    const __half2 slope = __float2half2_rn(0.01f);
    float acc = 0.f;
#pragma unroll
    for (int i = 0; i < 4; i++) {
        __half2 x = __hadd2(ph0[i], qh0[i]);
        x = __hmax2(x, __hmul2(x, slope));
        float2 f = __half22float2(x);
        acc = fmaf(f.x, wv[2 * i],     acc);
        acc = fmaf(f.y, wv[2 * i + 1], acc);
    }
#pragma unroll
    for (int i = 0; i < 4; i++) {
        __half2 x = __hadd2(ph1[i], qh1[i]);
        x = __hmax2(x, __hmul2(x, slope));
        float2 f = __half22float2(x);
        acc = fmaf(f.x, wv[8 + 2 * i],     acc);
        acc = fmaf(f.y, wv[8 + 2 * i + 1], acc);
    }
    acc += __shfl_xor_sync(0xFFFFFFFFu, acc, 4);
    acc += __shfl_xor_sync(0xFFFFFFFFu, acc, 2);
    acc += __shfl_xor_sync(0xFFFFFFFFu, acc, 1);

    if (valid && sub == 0) out[e] = acc + b_a2[0];
}

// ---------------------------------------------------------------------------
extern "C" void kernel_launch(void* const* d_in, const int* in_sizes, int n_in,
                              void* d_out, int out_size) {
    const float* node_feat = (const float*)d_in[0];
    const int*   src       = (const int*)  d_in[2];
    const int*   dst       = (const int*)  d_in[3];
    const float* W_node    = (const float*)d_in[4];
    const float* b_node    = (const float*)d_in[5];
    const float* W_a1      = (const float*)d_in[8];
    const float* b_a1      = (const float*)d_in[9];
    const float* W_a2      = (const float*)d_in[10];
    const float* b_a2      = (const float*)d_in[11];
    float* out = (float*)d_out;

    int E = in_sizes[2];
    int K = in_sizes[4] / CH;        // 118
    int M = in_sizes[0] / K;         // 10000

    {   // (K+1) rows -> 32-row tiles; 256 cols -> 32-col tiles
        dim3 g((K + 1 + 31) / 32, 8);
        build_wc_kernel<<<g, 256>>>(W_node, b_node, W_a1, b_a1, K);
    }
    {
        dim3 g((M + 127) / 128, 2);
        sgemm_bias_kernel<<<g, 256>>>(node_feat, M, K);
    }
    {
        int blocks = (E * 8 + 255) / 256;   // 4 edges/warp
        edge_kernel<<<blocks, 256>>>(src, dst, W_a2, b_a2, out, E);
    }
}

// round 5
// speedup vs baseline: 1.1951x; 1.1951x over previous
#include <cuda_runtime.h>
#include <cuda_fp16.h>
#include <cstdint>

// ---------------------------------------------------------------------------
// GATv2 collapsed:
//   out[e] = leaky_relu( P[src[e]] + Q[dst[e]] ) . w2 + b2
//   PQ = node_feat @ Wc + bc,  Wc = [W_node; b_node] @ W_a1 (biases folded)
// Layer loop idempotent; edge-hidden path dead. PQ stored fp16 (L2 traffic /2).
// ---------------------------------------------------------------------------

#define CH 128
#define MAX_NODES 10240
#define MAX_K 128

__device__ __half g_PQh[MAX_NODES * 2 * CH];   // per node: [P(128) | Q(128)] fp16
__device__ float  g_Wc[MAX_K * 2 * CH];        // combined weight [K, 256]
__device__ float  g_bc[2 * CH];                // combined bias   [256]

// packed fp32x2 FMA (Blackwell)
__device__ __forceinline__ void fma_f32x2(unsigned long long& d,
                                          unsigned long long a,
                                          unsigned long long b,
                                          unsigned long long c) {
    asm("fma.rn.f32x2 %0, %1, %2, %3;" : "=l"(d) : "l"(a), "l"(b), "l"(c));
}
__device__ __forceinline__ unsigned long long pack_f32x2(float lo, float hi) {
    unsigned long long r;
    asm("mov.b64 %0, {%1, %2};" : "=l"(r) : "r"(__float_as_uint(lo)), "r"(__float_as_uint(hi)));
    return r;
}
__device__ __forceinline__ void unpack_f32x2(unsigned long long v, float& lo, float& hi) {
    unsigned int a, b;
    asm("mov.b64 {%0, %1}, %2;" : "=r"(a), "=r"(b) : "l"(v));
    lo = __uint_as_float(a);
    hi = __uint_as_float(b);
}

// ---------------------------------------------------------------------------
// Kernel 1: Wc[119x256] = [W_node; b_node] @ W_a1-half.
// 64 blocks (4 row-tiles x 16 col-tiles of 16), 256 thr, 1x2-row micro-tile.
// ---------------------------------------------------------------------------
__global__ __launch_bounds__(256) void build_wc_kernel(
    const float* __restrict__ W_node,   // [K,128]
    const float* __restrict__ b_node,   // [128]
    const float* __restrict__ W_a1,     // [256,128]
    const float* __restrict__ b_a1,     // [128]
    int K) {
    __shared__ __align__(16) float As[32][128];   // 16 KB
    __shared__ __align__(16) float Bs[128][16];   // 8 KB

    int tid   = threadIdx.x;
    int kbase = blockIdx.x * 32;
    int jbase = blockIdx.y * 16;          // 0..240, never crosses the 128 split
    int half  = jbase >> 7;
    int jloc  = jbase & (CH - 1);

    // A tile: 32 rows x 128 floats = 1024 float4, 4 per thread (coalesced).
#pragma unroll
    for (int i = 0; i < 4; i++) {
        int id = tid + i * 256;
        int r  = id >> 5;
        int c4 = id & 31;
        int k  = kbase + r;
        float4 v = make_float4(0.f, 0.f, 0.f, 0.f);
        if (k < K)       v = ((const float4*)(W_node + (size_t)k * CH))[c4];
        else if (k == K) v = ((const float4*)b_node)[c4];
        *(float4*)&As[r][c4 * 4] = v;
    }
    // B tile: Bs[c][j] = W_a1[half*128 + c][jloc + j], 128x16 = 512 float4.
#pragma unroll
    for (int i = 0; i < 2; i++) {
        int id = tid + i * 256;
        int c  = id >> 2;                 // 0..127
        int j4 = id & 3;                  // float4 within 16-col slice
        float4 v = ((const float4*)(W_a1 + (size_t)(half * CH + c) * CH + jloc))[j4];
        *(float4*)&Bs[c][j4 * 4] = v;
    }
    __syncthreads();

    int c1 = tid & 15;                    // col
    int r1 = tid >> 4;                    // rows r1, r1+16
    float acc0 = 0.f, acc1 = 0.f;
#pragma unroll 8
    for (int k = 0; k < 128; k++) {
        float b0 = Bs[k][c1];
        acc0 = fmaf(As[r1][k],      b0, acc0);
        acc1 = fmaf(As[r1 + 16][k], b0, acc1);
    }

    int jj = jbase + c1;
#pragma unroll
    for (int i = 0; i < 2; i++) {
        int k = kbase + r1 + 16 * i;
        float a = (i == 0) ? acc0 : acc1;
        if (k < K) {
            g_Wc[(size_t)k * (2 * CH) + jj] = a;
        } else if (k == K) {
            g_bc[jj] = a + (half ? b_a1[jj - CH] : 0.f);
        }
    }
}

// ---------------------------------------------------------------------------
// Kernel 2: SGEMM  PQ[M,256] = node_feat[M,K] @ g_Wc[K,256] + g_bc  -> fp16
// 64x128 tile (314 blocks: fills the 148-SM chip), BK=8, 4x8 per thread via
// fp32x2 packed FMA, 256 threads, single-buffered.
// ---------------------------------------------------------------------------
__global__ __launch_bounds__(256) void sgemm_bias_kernel(
    const float* __restrict__ A, int M, int K) {
    const int N = 2 * CH;
    __shared__ __align__(16) float As[8][64];
    __shared__ __align__(16) float Bs[8][128];

    int brow = blockIdx.x * 64;
    int bcol = blockIdx.y * 128;
    int tid  = threadIdx.x;
    int tr   = (tid >> 4) * 4;       // 0..60
    int tc   = (tid & 15) * 8;       // 0..120

    unsigned long long acc64[4][4];
#pragma unroll
    for (int i = 0; i < 4; i++)
#pragma unroll
        for (int j = 0; j < 4; j++) acc64[i][j] = 0ull;

    int aRow = tid >> 2;             // 0..63
    int aK   = (tid & 3) * 2;        // 0,2,4,6
    int bK   = tid >> 5;             // 0..7
    int bN   = (tid & 31) * 4;       // 0..124
    int m    = brow + aRow;

    for (int k0 = 0; k0 < K; k0 += 8) {
#pragma unroll
        for (int i = 0; i < 2; i++) {
            int k = k0 + aK + i;
            As[aK + i][aRow] = (m < M && k < K) ? A[(size_t)m * K + k] : 0.f;
        }
        {
            int k = k0 + bK;
            float4 v = make_float4(0.f, 0.f, 0.f, 0.f);
            if (k < K) v = *(const float4*)&g_Wc[k * N + bcol + bN];
            *(float4*)&Bs[bK][bN] = v;
        }
        __syncthreads();
#pragma unroll
        for (int kk = 0; kk < 8; kk++) {
            float a[4];
            *(float4*)&a[0] = *(const float4*)&As[kk][tr];
            ulonglong2 t0 = *(const ulonglong2*)&Bs[kk][tc];
            ulonglong2 t1 = *(const ulonglong2*)&Bs[kk][tc + 4];
            unsigned long long b64[4] = {t0.x, t0.y, t1.x, t1.y};
#pragma unroll
            for (int i = 0; i < 4; i++) {
                unsigned long long aa = pack_f32x2(a[i], a[i]);
#pragma unroll
                for (int j = 0; j < 4; j++)
                    fma_f32x2(acc64[i][j], aa, b64[j], acc64[i][j]);
            }
        }
        __syncthreads();
    }

#pragma unroll
    for (int i = 0; i < 4; i++) {
        int mm = brow + tr + i;
        if (mm >= M) continue;
        __half2* orow = (__half2*)&g_PQh[(size_t)mm * N + bcol + tc];
#pragma unroll
        for (int j = 0; j < 4; j++) {
            int n = bcol + tc + 2 * j;
            float lo, hi;
            unpack_f32x2(acc64[i][j], lo, hi);
            lo += g_bc[n];
            hi += g_bc[n + 1];
            orow[j] = __floats2half2_rn(lo, hi);
        }
    }
}

// ---------------------------------------------------------------------------
// Kernel 3: per-edge (proven round-2/3 shape). 16 lanes per edge (2 edges/
// warp); lane owns 8 channels via one uint4 per operand. half2 add+leaky,
// fp32 dot + 4-step shuffle reduce.
// ---------------------------------------------------------------------------
__global__ __launch_bounds__(256) void edge_kernel(
    const int* __restrict__ src, const int* __restrict__ dst,
    const float* __restrict__ W_a2,   // [128]
    const float* __restrict__ b_a2,   // [1]
    float* __restrict__ out, int E) {
    int gwarp = (blockIdx.x * blockDim.x + threadIdx.x) >> 5;
    int lane  = threadIdx.x & 31;
    int sub   = lane & 15;
    int e     = gwarp * 2 + (lane >> 4);

    bool valid = (e < E);
    int ec = valid ? e : 0;
    int s = src[ec];
    int d = dst[ec];

    const uint4* PQ = (const uint4*)g_PQh;          // 32 uint4 per node row
    uint4 pv = PQ[(size_t)s * 32 + sub];            // P channels sub*8..+7
    uint4 qv = PQ[(size_t)d * 32 + 16 + sub];       // Q channels sub*8..+7
    float4 w0 = ((const float4*)W_a2)[sub * 2];
    float4 w1 = ((const float4*)W_a2)[sub * 2 + 1];

    const __half2* ph = (const __half2*)&pv;
    const __half2* qh = (const __half2*)&qv;
    float wv[8] = {w0.x, w0.y, w0.z, w0.w, w1.x, w1.y, w1.z, w1.w};

    const __half2 slope = __float2half2_rn(0.01f);
    float acc = 0.f;
#pragma unroll
    for (int i = 0; i < 4; i++) {
        __half2 x = __hadd2(ph[i], qh[i]);
        x = __hmax2(x, __hmul2(x, slope));          // leaky_relu
        float2 f = __half22float2(x);
        acc = fmaf(f.x, wv[2 * i],     acc);
        acc = fmaf(f.y, wv[2 * i + 1], acc);
    }
    acc += __shfl_xor_sync(0xFFFFFFFFu, acc, 8);
    acc += __shfl_xor_sync(0xFFFFFFFFu, acc, 4);
    acc += __shfl_xor_sync(0xFFFFFFFFu, acc, 2);
    acc += __shfl_xor_sync(0xFFFFFFFFu, acc, 1);

    if (valid && sub == 0) out[e] = acc + b_a2[0];
}

// ---------------------------------------------------------------------------
extern "C" void kernel_launch(void* const* d_in, const int* in_sizes, int n_in,
                              void* d_out, int out_size) {
    const float* node_feat = (const float*)d_in[0];
    const int*   src       = (const int*)  d_in[2];
    const int*   dst       = (const int*)  d_in[3];
    const float* W_node    = (const float*)d_in[4];
    const float* b_node    = (const float*)d_in[5];
    const float* W_a1      = (const float*)d_in[8];
    const float* b_a1      = (const float*)d_in[9];
    const float* W_a2      = (const float*)d_in[10];
    const float* b_a2      = (const float*)d_in[11];
    float* out = (float*)d_out;

    int E = in_sizes[2];
    int K = in_sizes[4] / CH;        // 118
    int M = in_sizes[0] / K;         // 10000

    {   // (K+1) rows -> 32-row tiles; 256 cols -> 16-col tiles
        dim3 g((K + 1 + 31) / 32, 16);
        build_wc_kernel<<<g, 256>>>(W_node, b_node, W_a1, b_a1, K);
    }
    {
        dim3 g((M + 63) / 64, 2);    // 314 blocks: fills the chip
        sgemm_bias_kernel<<<g, 256>>>(node_feat, M, K);
    }
    {
        int blocks = (E * 16 + 255) / 256;   // 2 edges/warp
        edge_kernel<<<blocks, 256>>>(src, dst, W_a2, b_a2, out, E);
    }
}

// round 6
// speedup vs baseline: 1.4596x; 1.2213x over previous
#include <cuda_runtime.h>
#include <cuda_fp16.h>
#include <cstdint>

// ---------------------------------------------------------------------------
// GATv2 collapsed:
//   out[e] = leaky_relu( P[src[e]] + Q[dst[e]] ) . w2 + b2
//   PQ = node_feat @ Wc + bc,  Wc = [W_node; b_node] @ W_a1 (biases folded)
// Layer loop idempotent; edge-hidden path dead. PQ stored fp16 (L2 traffic /2).
// ---------------------------------------------------------------------------

#define CH 128
#define MAX_NODES 10240
#define MAX_K 128

__device__ __half g_PQh[MAX_NODES * 2 * CH];   // per node: [P(128) | Q(128)] fp16
__device__ float  g_Wc[MAX_K * 2 * CH];        // combined weight [K, 256]
__device__ float  g_bc[2 * CH];                // combined bias   [256]

// packed fp32x2 FMA (Blackwell)
__device__ __forceinline__ void fma_f32x2(unsigned long long& d,
                                          unsigned long long a,
                                          unsigned long long b,
                                          unsigned long long c) {
    asm("fma.rn.f32x2 %0, %1, %2, %3;" : "=l"(d) : "l"(a), "l"(b), "l"(c));
}
__device__ __forceinline__ unsigned long long pack_f32x2(float lo, float hi) {
    unsigned long long r;
    asm("mov.b64 %0, {%1, %2};" : "=l"(r) : "r"(__float_as_uint(lo)), "r"(__float_as_uint(hi)));
    return r;
}
__device__ __forceinline__ void unpack_f32x2(unsigned long long v, float& lo, float& hi) {
    unsigned int a, b;
    asm("mov.b64 {%0, %1}, %2;" : "=r"(a), "=r"(b) : "l"(v));
    lo = __uint_as_float(a);
    hi = __uint_as_float(b);
}

// ---------------------------------------------------------------------------
// Kernel 1 (r5 proven): Wc[119x256] = [W_node; b_node] @ W_a1-half.
// 64 blocks (4 row-tiles x 16 col-tiles of 16), 256 thr, 1x2-row micro-tile.
// ---------------------------------------------------------------------------
__global__ __launch_bounds__(256) void build_wc_kernel(
    const float* __restrict__ W_node,   // [K,128]
    const float* __restrict__ b_node,   // [128]
    const float* __restrict__ W_a1,     // [256,128]
    const float* __restrict__ b_a1,     // [128]
    int K) {
    __shared__ __align__(16) float As[32][128];   // 16 KB
    __shared__ __align__(16) float Bs[128][16];   // 8 KB

    int tid   = threadIdx.x;
    int kbase = blockIdx.x * 32;
    int jbase = blockIdx.y * 16;
    int half  = jbase >> 7;
    int jloc  = jbase & (CH - 1);

#pragma unroll
    for (int i = 0; i < 4; i++) {
        int id = tid + i * 256;
        int r  = id >> 5;
        int c4 = id & 31;
        int k  = kbase + r;
        float4 v = make_float4(0.f, 0.f, 0.f, 0.f);
        if (k < K)       v = ((const float4*)(W_node + (size_t)k * CH))[c4];
        else if (k == K) v = ((const float4*)b_node)[c4];
        *(float4*)&As[r][c4 * 4] = v;
    }
#pragma unroll
    for (int i = 0; i < 2; i++) {
        int id = tid + i * 256;
        int c  = id >> 2;
        int j4 = id & 3;
        float4 v = ((const float4*)(W_a1 + (size_t)(half * CH + c) * CH + jloc))[j4];
        *(float4*)&Bs[c][j4 * 4] = v;
    }
    __syncthreads();

    int c1 = tid & 15;
    int r1 = tid >> 4;
    float acc0 = 0.f, acc1 = 0.f;
#pragma unroll 8
    for (int k = 0; k < 128; k++) {
        float b0 = Bs[k][c1];
        acc0 = fmaf(As[r1][k],      b0, acc0);
        acc1 = fmaf(As[r1 + 16][k], b0, acc1);
    }

    int jj = jbase + c1;
#pragma unroll
    for (int i = 0; i < 2; i++) {
        int k = kbase + r1 + 16 * i;
        float a = (i == 0) ? acc0 : acc1;
        if (k < K) {
            g_Wc[(size_t)k * (2 * CH) + jj] = a;
        } else if (k == K) {
            g_bc[jj] = a + (half ? b_a1[jj - CH] : 0.f);
        }
    }
}

// ---------------------------------------------------------------------------
// Kernel 2 (r2/r3 proven): SGEMM PQ[M,256] = node_feat @ g_Wc + g_bc -> fp16
// 128x128 tile, BK=8, 8x8 per thread via fp32x2 packed FMA, 256 threads.
// ---------------------------------------------------------------------------
__global__ __launch_bounds__(256) void sgemm_bias_kernel(
    const float* __restrict__ A, int M, int K) {
    const int N = 2 * CH;
    __shared__ __align__(16) float As[8][128];
    __shared__ __align__(16) float Bs[8][128];

    int brow = blockIdx.x * 128;
    int bcol = blockIdx.y * 128;
    int tid  = threadIdx.x;
    int tr   = (tid >> 4) * 8;
    int tc   = (tid & 15) * 8;

    unsigned long long acc64[8][4];
#pragma unroll
    for (int i = 0; i < 8; i++)
#pragma unroll
        for (int j = 0; j < 4; j++) acc64[i][j] = 0ull;

    int aRow = tid >> 1;
    int aK   = (tid & 1) * 4;
    int bK   = tid >> 5;
    int bN   = (tid & 31) * 4;

    for (int k0 = 0; k0 < K; k0 += 8) {
        int m = brow + aRow;
#pragma unroll
        for (int i = 0; i < 4; i++) {
            int k = k0 + aK + i;
            As[aK + i][aRow] = (m < M && k < K) ? A[(size_t)m * K + k] : 0.f;
        }
        {
            int k = k0 + bK;
            float4 v = make_float4(0.f, 0.f, 0.f, 0.f);
            if (k < K) v = *(const float4*)&g_Wc[k * N + bcol + bN];
            *(float4*)&Bs[bK][bN] = v;
        }
        __syncthreads();
#pragma unroll
        for (int kk = 0; kk < 8; kk++) {
            float a[8];
            *(float4*)&a[0] = *(const float4*)&As[kk][tr];
            *(float4*)&a[4] = *(const float4*)&As[kk][tr + 4];
            ulonglong2 t0 = *(const ulonglong2*)&Bs[kk][tc];
            ulonglong2 t1 = *(const ulonglong2*)&Bs[kk][tc + 4];
            unsigned long long b64[4] = {t0.x, t0.y, t1.x, t1.y};
#pragma unroll
            for (int i = 0; i < 8; i++) {
                unsigned long long aa = pack_f32x2(a[i], a[i]);
#pragma unroll
                for (int j = 0; j < 4; j++)
                    fma_f32x2(acc64[i][j], aa, b64[j], acc64[i][j]);
            }
        }
        __syncthreads();
    }

#pragma unroll
    for (int i = 0; i < 8; i++) {
        int m = brow + tr + i;
        if (m >= M) continue;
        __half2* orow = (__half2*)&g_PQh[(size_t)m * N + bcol + tc];
#pragma unroll
        for (int j = 0; j < 4; j++) {
            int n = bcol + tc + 2 * j;
            float lo, hi;
            unpack_f32x2(acc64[i][j], lo, hi);
            lo += g_bc[n];
            hi += g_bc[n + 1];
            orow[j] = __floats2half2_rn(lo, hi);
        }
    }
}

// ---------------------------------------------------------------------------
// Kernel 3: per-edge, 16 lanes/edge but 4 edges per warp (2 pairs), ALL loads
// issued before any compute -> MLP 4 with fully contiguous 256 B row reads.
// half2 add+leaky, fp32 dot + 4-step shuffle reduce (both pairs share shuffles).
// ---------------------------------------------------------------------------
__global__ __launch_bounds__(256) void edge_kernel(
    const int* __restrict__ src, const int* __restrict__ dst,
    const float* __restrict__ W_a2,   // [128]
    const float* __restrict__ b_a2,   // [1]
    float* __restrict__ out, int E) {
    int gwarp = (blockIdx.x * blockDim.x + threadIdx.x) >> 5;
    int lane  = threadIdx.x & 31;
    int sub   = lane & 15;            // channel group within edge
    int hw    = lane >> 4;            // which edge of the pair

    int e0 = gwarp * 4 + hw;          // first pair
    int e1 = e0 + 2;                  // second pair

    bool v0 = (e0 < E);
    bool v1 = (e1 < E);
    int ec0 = v0 ? e0 : 0;
    int ec1 = v1 ? e1 : 0;

    int s0 = src[ec0], d0 = dst[ec0];
    int s1 = src[ec1], d1 = dst[ec1];

    const uint4* PQ = (const uint4*)g_PQh;          // 32 uint4 per node row
    // Issue all four 128-bit loads up front (MLP 4)
    uint4 pv0 = PQ[(size_t)s0 * 32 + sub];
    uint4 qv0 = PQ[(size_t)d0 * 32 + 16 + sub];
    uint4 pv1 = PQ[(size_t)s1 * 32 + sub];
    uint4 qv1 = PQ[(size_t)d1 * 32 + 16 + sub];

    float4 w0 = ((const float4*)W_a2)[sub * 2];
    float4 w1 = ((const float4*)W_a2)[sub * 2 + 1];
    float wv[8] = {w0.x, w0.y, w0.z, w0.w, w1.x, w1.y, w1.z, w1.w};

    const __half2 slope = __float2half2_rn(0.01f);

    const __half2* ph0 = (const __half2*)&pv0;
    const __half2* qh0 = (const __half2*)&qv0;
    const __half2* ph1 = (const __half2*)&pv1;
    const __half2* qh1 = (const __half2*)&qv1;

    float acc0 = 0.f, acc1 = 0.f;
#pragma unroll
    for (int i = 0; i < 4; i++) {
        __half2 x = __hadd2(ph0[i], qh0[i]);
        x = __hmax2(x, __hmul2(x, slope));
        float2 f = __half22float2(x);
        acc0 = fmaf(f.x, wv[2 * i],     acc0);
        acc0 = fmaf(f.y, wv[2 * i + 1], acc0);

        __half2 y = __hadd2(ph1[i], qh1[i]);
        y = __hmax2(y, __hmul2(y, slope));
        float2 g = __half22float2(y);
        acc1 = fmaf(g.x, wv[2 * i],     acc1);
        acc1 = fmaf(g.y, wv[2 * i + 1], acc1);
    }
#pragma unroll
    for (int off = 8; off; off >>= 1) {
        acc0 += __shfl_xor_sync(0xFFFFFFFFu, acc0, off);
        acc1 += __shfl_xor_sync(0xFFFFFFFFu, acc1, off);
    }

    if (sub == 0) {
        float b2 = b_a2[0];
        if (v0) out[e0] = acc0 + b2;
        if (v1) out[e1] = acc1 + b2;
    }
}

// ---------------------------------------------------------------------------
extern "C" void kernel_launch(void* const* d_in, const int* in_sizes, int n_in,
                              void* d_out, int out_size) {
    const float* node_feat = (const float*)d_in[0];
    const int*   src       = (const int*)  d_in[2];
    const int*   dst       = (const int*)  d_in[3];
    const float* W_node    = (const float*)d_in[4];
    const float* b_node    = (const float*)d_in[5];
    const float* W_a1      = (const float*)d_in[8];
    const float* b_a1      = (const float*)d_in[9];
    const float* W_a2      = (const float*)d_in[10];
    const float* b_a2      = (const float*)d_in[11];
    float* out = (float*)d_out;

    int E = in_sizes[2];
    int K = in_sizes[4] / CH;        // 118
    int M = in_sizes[0] / K;         // 10000

    {
        dim3 g((K + 1 + 31) / 32, 16);
        build_wc_kernel<<<g, 256>>>(W_node, b_node, W_a1, b_a1, K);
    }
    {
        dim3 g((M + 127) / 128, 2);
        sgemm_bias_kernel<<<g, 256>>>(node_feat, M, K);
    }
    {
        int nwarps  = (E + 3) / 4;              // 4 edges per warp
        int blocks  = (nwarps * 32 + 255) / 256;
        edge_kernel<<<blocks, 256>>>(src, dst, W_a2, b_a2, out, E);
    }
}

// round 10
// speedup vs baseline: 1.5366x; 1.0528x over previous
#include <cuda_runtime.h>
#include <cuda_fp16.h>
#include <cstdint>

// ---------------------------------------------------------------------------
// GATv2 collapsed:
//   out[e] = leaky_relu( P[src[e]] + Q[dst[e]] ) . w2 + b2
//   PQ = node_feat @ Wc + bc,  Wc = [W_node; b_node] @ W_a1 (biases folded)
// Layer loop idempotent; edge-hidden path dead. PQ stored fp16 (L2 traffic /2).
// ---------------------------------------------------------------------------

#define CH 128
#define MAX_NODES 10240
#define MAX_K 128

__device__ __half g_PQh[MAX_NODES * 2 * CH];   // per node: [P(128) | Q(128)] fp16
__device__ float  g_Wc[MAX_K * 2 * CH];        // combined weight [K, 256]
__device__ float  g_bc[2 * CH];                // combined bias   [256]

// packed fp32x2 FMA (Blackwell)
__device__ __forceinline__ void fma_f32x2(unsigned long long& d,
                                          unsigned long long a,
                                          unsigned long long b,
                                          unsigned long long c) {
    asm("fma.rn.f32x2 %0, %1, %2, %3;" : "=l"(d) : "l"(a), "l"(b), "l"(c));
}
__device__ __forceinline__ unsigned long long pack_f32x2(float lo, float hi) {
    unsigned long long r;
    asm("mov.b64 %0, {%1, %2};" : "=l"(r) : "r"(__float_as_uint(lo)), "r"(__float_as_uint(hi)));
    return r;
}
__device__ __forceinline__ void unpack_f32x2(unsigned long long v, float& lo, float& hi) {
    unsigned int a, b;
    asm("mov.b64 {%0, %1}, %2;" : "=r"(a), "=r"(b) : "l"(v));
    lo = __uint_as_float(a);
    hi = __uint_as_float(b);
}

// ---------------------------------------------------------------------------
// Kernel 1 (proven): Wc[119x256] = [W_node; b_node] @ W_a1-half.
// 64 blocks (4 row-tiles x 16 col-tiles of 16), 256 thr, 1x2-row micro-tile.
// ---------------------------------------------------------------------------
__global__ __launch_bounds__(256) void build_wc_kernel(
    const float* __restrict__ W_node,   // [K,128]
    const float* __restrict__ b_node,   // [128]
    const float* __restrict__ W_a1,     // [256,128]
    const float* __restrict__ b_a1,     // [128]
    int K) {
    __shared__ __align__(16) float As[32][128];
    __shared__ __align__(16) float Bs[128][16];

    int tid   = threadIdx.x;
    int kbase = blockIdx.x * 32;
    int jbase = blockIdx.y * 16;
    int half  = jbase >> 7;
    int jloc  = jbase & (CH - 1);

#pragma unroll
    for (int i = 0; i < 4; i++) {
        int id = tid + i * 256;
        int r  = id >> 5;
        int c4 = id & 31;
        int k  = kbase + r;
        float4 v = make_float4(0.f, 0.f, 0.f, 0.f);
        if (k < K)       v = ((const float4*)(W_node + (size_t)k * CH))[c4];
        else if (k == K) v = ((const float4*)b_node)[c4];
        *(float4*)&As[r][c4 * 4] = v;
    }
#pragma unroll
    for (int i = 0; i < 2; i++) {
        int id = tid + i * 256;
        int c  = id >> 2;
        int j4 = id & 3;
        float4 v = ((const float4*)(W_a1 + (size_t)(half * CH + c) * CH + jloc))[j4];
        *(float4*)&Bs[c][j4 * 4] = v;
    }
    __syncthreads();

    int c1 = tid & 15;
    int r1 = tid >> 4;
    float acc0 = 0.f, acc1 = 0.f;
#pragma unroll 8
    for (int k = 0; k < 128; k++) {
        float b0 = Bs[k][c1];
        acc0 = fmaf(As[r1][k],      b0, acc0);
        acc1 = fmaf(As[r1 + 16][k], b0, acc1);
    }

    int jj = jbase + c1;
#pragma unroll
    for (int i = 0; i < 2; i++) {
        int k = kbase + r1 + 16 * i;
        float a = (i == 0) ? acc0 : acc1;
        if (k < K) {
            g_Wc[(size_t)k * (2 * CH) + jj] = a;
        } else if (k == K) {
            g_bc[jj] = a + (half ? b_a1[jj - CH] : 0.f);
        }
    }
}

// ---------------------------------------------------------------------------
// Kernel 2 (proven r2/r3/r6): SGEMM PQ[M,256] = node_feat @ g_Wc + g_bc -> fp16
// 128x128 tile, BK=8, 8x8 per thread via fp32x2 packed FMA, 256 threads.
// ---------------------------------------------------------------------------
__global__ __launch_bounds__(256) void sgemm_bias_kernel(
    const float* __restrict__ A, int M, int K) {
    const int N = 2 * CH;
    __shared__ __align__(16) float As[8][128];
    __shared__ __align__(16) float Bs[8][128];

    int brow = blockIdx.x * 128;
    int bcol = blockIdx.y * 128;
    int tid  = threadIdx.x;
    int tr   = (tid >> 4) * 8;
    int tc   = (tid & 15) * 8;

    unsigned long long acc64[8][4];
#pragma unroll
    for (int i = 0; i < 8; i++)
#pragma unroll
        for (int j = 0; j < 4; j++) acc64[i][j] = 0ull;

    int aRow = tid >> 1;
    int aK   = (tid & 1) * 4;
    int bK   = tid >> 5;
    int bN   = (tid & 31) * 4;

    for (int k0 = 0; k0 < K; k0 += 8) {
        int m = brow + aRow;
#pragma unroll
        for (int i = 0; i < 4; i++) {
            int k = k0 + aK + i;
            As[aK + i][aRow] = (m < M && k < K) ? A[(size_t)m * K + k] : 0.f;
        }
        {
            int k = k0 + bK;
            float4 v = make_float4(0.f, 0.f, 0.f, 0.f);
            if (k < K) v = *(const float4*)&g_Wc[k * N + bcol + bN];
            *(float4*)&Bs[bK][bN] = v;
        }
        __syncthreads();
#pragma unroll
        for (int kk = 0; kk < 8; kk++) {
            float a[8];
            *(float4*)&a[0] = *(const float4*)&As[kk][tr];
            *(float4*)&a[4] = *(const float4*)&As[kk][tr + 4];
            ulonglong2 t0 = *(const ulonglong2*)&Bs[kk][tc];
            ulonglong2 t1 = *(const ulonglong2*)&Bs[kk][tc + 4];
            unsigned long long b64[4] = {t0.x, t0.y, t1.x, t1.y};
#pragma unroll
            for (int i = 0; i < 8; i++) {
                unsigned long long aa = pack_f32x2(a[i], a[i]);
#pragma unroll
                for (int j = 0; j < 4; j++)
                    fma_f32x2(acc64[i][j], aa, b64[j], acc64[i][j]);
            }
        }
        __syncthreads();
    }

#pragma unroll
    for (int i = 0; i < 8; i++) {
        int m = brow + tr + i;
        if (m >= M) continue;
        __half2* orow = (__half2*)&g_PQh[(size_t)m * N + bcol + tc];
#pragma unroll
        for (int j = 0; j < 4; j++) {
            int n = bcol + tc + 2 * j;
            float lo, hi;
            unpack_f32x2(acc64[i][j], lo, hi);
            lo += g_bc[n];
            hi += g_bc[n + 1];
            orow[j] = __floats2half2_rn(lo, hi);
        }
    }
}

// ---------------------------------------------------------------------------
// Kernel 3: per-edge, 16 lanes/edge, 8 edges per warp (4 pairs). ALL 16
// LDG.128 issued before any compute -> MLP 8, contiguous 256 B row reads.
// half2 add+leaky, fp32 dot + shared 4-step shuffle reduce.
// ---------------------------------------------------------------------------
__global__ __launch_bounds__(256) void edge_kernel(
    const int* __restrict__ src, const int* __restrict__ dst,
    const float* __restrict__ W_a2,   // [128]
    const float* __restrict__ b_a2,   // [1]
    float* __restrict__ out, int E) {
    int gwarp = (blockIdx.x * blockDim.x + threadIdx.x) >> 5;
    int lane  = threadIdx.x & 31;
    int sub   = lane & 15;            // channel group within edge
    int hw    = lane >> 4;            // which edge of each pair

    int eb = gwarp * 8 + hw;          // edges eb, eb+2, eb+4, eb+6

    int  ee[4];
    bool vv[4];
#pragma unroll
    for (int j = 0; j < 4; j++) {
        ee[j] = eb + 2 * j;
        vv[j] = (ee[j] < E);
    }

    int sidx[4], didx[4];
#pragma unroll
    for (int j = 0; j < 4; j++) {
        int ec  = vv[j] ? ee[j] : 0;
        sidx[j] = src[ec];
        didx[j] = dst[ec];
    }

    const uint4* PQ = (const uint4*)g_PQh;          // 32 uint4 per node row
    // Issue all 8 P/Q row loads (16 LDG.128 across the batch) up front.
    uint4 pv[4], qv[4];
#pragma unroll
    for (int j = 0; j < 4; j++) {
        pv[j] = PQ[(size_t)sidx[j] * 32 + sub];
        qv[j] = PQ[(size_t)didx[j] * 32 + 16 + sub];
    }

    float4 w0 = ((const float4*)W_a2)[sub * 2];
    float4 w1 = ((const float4*)W_a2)[sub * 2 + 1];
    float wv[8] = {w0.x, w0.y, w0.z, w0.w, w1.x, w1.y, w1.z, w1.w};

    const __half2 slope = __float2half2_rn(0.01f);

    float acc[4] = {0.f, 0.f, 0.f, 0.f};
#pragma unroll
    for (int j = 0; j < 4; j++) {
        const __half2* ph = (const __half2*)&pv[j];
        const __half2* qh = (const __half2*)&qv[j];
#pragma unroll
        for (int i = 0; i < 4; i++) {
            __half2 x = __hadd2(ph[i], qh[i]);
            x = __hmax2(x, __hmul2(x, slope));
            float2 f = __half22float2(x);
            acc[j] = fmaf(f.x, wv[2 * i],     acc[j]);
            acc[j] = fmaf(f.y, wv[2 * i + 1], acc[j]);
        }
    }
#pragma unroll
    for (int off = 8; off; off >>= 1) {
#pragma unroll
        for (int j = 0; j < 4; j++)
            acc[j] += __shfl_xor_sync(0xFFFFFFFFu, acc[j], off);
    }

    if (sub == 0) {
        float b2 = b_a2[0];
#pragma unroll
        for (int j = 0; j < 4; j++)
            if (vv[j]) out[ee[j]] = acc[j] + b2;
    }
}

// ---------------------------------------------------------------------------
extern "C" void kernel_launch(void* const* d_in, const int* in_sizes, int n_in,
                              void* d_out, int out_size) {
    const float* node_feat = (const float*)d_in[0];
    const int*   src       = (const int*)  d_in[2];
    const int*   dst       = (const int*)  d_in[3];
    const float* W_node    = (const float*)d_in[4];
    const float* b_node    = (const float*)d_in[5];
    const float* W_a1      = (const float*)d_in[8];
    const float* b_a1      = (const float*)d_in[9];
    const float* W_a2      = (const float*)d_in[10];
    const float* b_a2      = (const float*)d_in[11];
    float* out = (float*)d_out;

    int E = in_sizes[2];
    int K = in_sizes[4] / CH;        // 118
    int M = in_sizes[0] / K;         // 10000

    {
        dim3 g((K + 1 + 31) / 32, 16);
        build_wc_kernel<<<g, 256>>>(W_node, b_node, W_a1, b_a1, K);
    }
    {
        dim3 g((M + 127) / 128, 2);
        sgemm_bias_kernel<<<g, 256>>>(node_feat, M, K);
    }
    {
        int nwarps = (E + 7) / 8;               // 8 edges per warp
        int blocks = (nwarps * 32 + 255) / 256;
        edge_kernel<<<blocks, 256>>>(src, dst, W_a2, b_a2, out, E);
    }
}

// round 11
// speedup vs baseline: 1.9126x; 1.2447x over previous
#include <cuda_runtime.h>
#include <cuda_fp16.h>
#include <cstdint>

// ---------------------------------------------------------------------------
// GATv2 collapsed:
//   out[e] = leaky_relu( P[src[e]] + Q[dst[e]] ) . w2 + b2
//   PQ = node_feat @ Wc + bc,  Wc = [W_node; b_node] @ W_a1 (biases folded)
// Layer loop idempotent; edge-hidden path dead. PQ stored fp16.
// SGEMM on tensor cores (tf32 mma.sync.m16n8k8).
// ---------------------------------------------------------------------------

#define CH 128
#define MAX_NODES 10240
#define MAX_K 128

__device__ __half g_PQh[MAX_NODES * 2 * CH];   // per node: [P(128) | Q(128)] fp16
__device__ float  g_Wc[MAX_K * 2 * CH];        // combined weight [K, 256]
__device__ float  g_bc[2 * CH];                // combined bias   [256]

__device__ __forceinline__ unsigned int f32_to_tf32(float f) {
    unsigned int r;
    asm("cvt.rna.tf32.f32 %0, %1;" : "=r"(r) : "f"(f));
    return r;
}

__device__ __forceinline__ void mma_tf32_16x8x8(
    float& d0, float& d1, float& d2, float& d3,
    unsigned int a0, unsigned int a1, unsigned int a2, unsigned int a3,
    unsigned int b0, unsigned int b1) {
    asm volatile(
        "mma.sync.aligned.m16n8k8.row.col.f32.tf32.tf32.f32 "
        "{%0,%1,%2,%3}, {%4,%5,%6,%7}, {%8,%9}, {%0,%1,%2,%3};"
        : "+f"(d0), "+f"(d1), "+f"(d2), "+f"(d3)
        : "r"(a0), "r"(a1), "r"(a2), "r"(a3), "r"(b0), "r"(b1));
}

// ---------------------------------------------------------------------------
// Kernel 1 (proven): Wc[119x256] = [W_node; b_node] @ W_a1-half.
// ---------------------------------------------------------------------------
__global__ __launch_bounds__(256) void build_wc_kernel(
    const float* __restrict__ W_node,   // [K,128]
    const float* __restrict__ b_node,   // [128]
    const float* __restrict__ W_a1,     // [256,128]
    const float* __restrict__ b_a1,     // [128]
    int K) {
    __shared__ __align__(16) float As[32][128];
    __shared__ __align__(16) float Bs[128][16];

    int tid   = threadIdx.x;
    int kbase = blockIdx.x * 32;
    int jbase = blockIdx.y * 16;
    int half  = jbase >> 7;
    int jloc  = jbase & (CH - 1);

#pragma unroll
    for (int i = 0; i < 4; i++) {
        int id = tid + i * 256;
        int r  = id >> 5;
        int c4 = id & 31;
        int k  = kbase + r;
        float4 v = make_float4(0.f, 0.f, 0.f, 0.f);
        if (k < K)       v = ((const float4*)(W_node + (size_t)k * CH))[c4];
        else if (k == K) v = ((const float4*)b_node)[c4];
        *(float4*)&As[r][c4 * 4] = v;
    }
#pragma unroll
    for (int i = 0; i < 2; i++) {
        int id = tid + i * 256;
        int c  = id >> 2;
        int j4 = id & 3;
        float4 v = ((const float4*)(W_a1 + (size_t)(half * CH + c) * CH + jloc))[j4];
        *(float4*)&Bs[c][j4 * 4] = v;
    }
    __syncthreads();

    int c1 = tid & 15;
    int r1 = tid >> 4;
    float acc0 = 0.f, acc1 = 0.f;
#pragma unroll 8
    for (int k = 0; k < 128; k++) {
        float b0 = Bs[k][c1];
        acc0 = fmaf(As[r1][k],      b0, acc0);
        acc1 = fmaf(As[r1 + 16][k], b0, acc1);
    }

    int jj = jbase + c1;
#pragma unroll
    for (int i = 0; i < 2; i++) {
        int k = kbase + r1 + 16 * i;
        float a = (i == 0) ? acc0 : acc1;
        if (k < K) {
            g_Wc[(size_t)k * (2 * CH) + jj] = a;
        } else if (k == K) {
            g_bc[jj] = a + (half ? b_a1[jj - CH] : 0.f);
        }
    }
}

// ---------------------------------------------------------------------------
// Kernel 2: tensor-core SGEMM  PQ[M,256] = node_feat[M,K] @ g_Wc + g_bc -> fp16
// tf32 mma.sync.m16n8k8. Block tile 128x128, 8 warps (4M x 2N), warp 32x64.
// K staged in chunks of 16; smem pads chosen conflict-free for frag loads.
// ---------------------------------------------------------------------------
__global__ __launch_bounds__(256) void sgemm_tc_kernel(
    const float* __restrict__ A, int M, int K) {
    const int N = 2 * CH;
    __shared__ unsigned int As[128][20];    // [row][k], tf32 bits, pad 20
    __shared__ unsigned int Bs[16][136];    // [k][col], tf32 bits, pad 136

    int tid  = threadIdx.x;
    int brow = blockIdx.x * 128;
    int bcol = blockIdx.y * 128;

    int w    = tid >> 5;
    int lane = tid & 31;
    int wm   = w & 3;          // 0..3 -> M offset wm*32
    int wn   = w >> 2;         // 0..1 -> N offset wn*64
    int g    = lane >> 2;      // groupID 0..7
    int tg   = lane & 3;       // thread-in-group 0..3

    float acc[2][8][4];        // [m-tile][n-tile][c0..c3]
#pragma unroll
    for (int i = 0; i < 2; i++)
#pragma unroll
        for (int j = 0; j < 8; j++)
#pragma unroll
            for (int c = 0; c < 4; c++) acc[i][j][c] = 0.f;

    for (int k0 = 0; k0 < K; k0 += 16) {
        // Stage A chunk: 128 rows x 16 k (coalesced: lanes sweep k then rows)
#pragma unroll
        for (int i = 0; i < 8; i++) {
            int id = tid + i * 256;      // 0..2047
            int r  = id >> 4;
            int k  = id & 15;
            int m  = brow + r;
            float v = 0.f;
            if (m < M && (k0 + k) < K) v = A[(size_t)m * K + k0 + k];
            As[r][k] = f32_to_tf32(v);
        }
        // Stage B chunk: 16 k x 128 cols
#pragma unroll
        for (int i = 0; i < 8; i++) {
            int id = tid + i * 256;      // 0..2047
            int k  = id >> 7;
            int n  = id & 127;
            float v = 0.f;
            if ((k0 + k) < K) v = g_Wc[(size_t)(k0 + k) * N + bcol + n];
            Bs[k][n] = f32_to_tf32(v);
        }
        __syncthreads();

#pragma unroll
        for (int ks = 0; ks < 2; ks++) {
            int kb = ks * 8;
            // A fragments for the two m16 tiles
            unsigned int af[2][4];
#pragma unroll
            for (int mt = 0; mt < 2; mt++) {
                int r0 = wm * 32 + mt * 16;
                af[mt][0] = As[r0 + g][kb + tg];
                af[mt][1] = As[r0 + g + 8][kb + tg];
                af[mt][2] = As[r0 + g][kb + tg + 4];
                af[mt][3] = As[r0 + g + 8][kb + tg + 4];
            }
#pragma unroll
            for (int nt = 0; nt < 8; nt++) {
                int n0 = wn * 64 + nt * 8;
                unsigned int b0 = Bs[kb + tg][n0 + g];
                unsigned int b1 = Bs[kb + tg + 4][n0 + g];
#pragma unroll
                for (int mt = 0; mt < 2; mt++) {
                    mma_tf32_16x8x8(acc[mt][nt][0], acc[mt][nt][1],
                                    acc[mt][nt][2], acc[mt][nt][3],
                                    af[mt][0], af[mt][1], af[mt][2], af[mt][3],
                                    b0, b1);
                }
            }
        }
        __syncthreads();
    }

    // Epilogue: add bias, convert to fp16, store half2 pairs.
#pragma unroll
    for (int mt = 0; mt < 2; mt++) {
#pragma unroll
        for (int nt = 0; nt < 8; nt++) {
            int col  = bcol + wn * 64 + nt * 8 + tg * 2;
            float b0 = g_bc[col];
            float b1 = g_bc[col + 1];
            int row0 = brow + wm * 32 + mt * 16 + g;
            int row1 = row0 + 8;
            if (row0 < M) {
                __half2 h = __floats2half2_rn(acc[mt][nt][0] + b0,
                                              acc[mt][nt][1] + b1);
                *(__half2*)&g_PQh[(size_t)row0 * N + col] = h;
            }
            if (row1 < M) {
                __half2 h = __floats2half2_rn(acc[mt][nt][2] + b0,
                                              acc[mt][nt][3] + b1);
                *(__half2*)&g_PQh[(size_t)row1 * N + col] = h;
            }
        }
    }
}

// ---------------------------------------------------------------------------
// Kernel 3 (proven r10): 16 lanes/edge, 8 edges per warp, MLP 8.
// ---------------------------------------------------------------------------
__global__ __launch_bounds__(256) void edge_kernel(
    const int* __restrict__ src, const int* __restrict__ dst,
    const float* __restrict__ W_a2,   // [128]
    const float* __restrict__ b_a2,   // [1]
    float* __restrict__ out, int E) {
    int gwarp = (blockIdx.x * blockDim.x + threadIdx.x) >> 5;
    int lane  = threadIdx.x & 31;
    int sub   = lane & 15;
    int hw    = lane >> 4;

    int eb = gwarp * 8 + hw;

    int  ee[4];
    bool vv[4];
#pragma unroll
    for (int j = 0; j < 4; j++) {
        ee[j] = eb + 2 * j;
        vv[j] = (ee[j] < E);
    }

    int sidx[4], didx[4];
#pragma unroll
    for (int j = 0; j < 4; j++) {
        int ec  = vv[j] ? ee[j] : 0;
        sidx[j] = src[ec];
        didx[j] = dst[ec];
    }

    const uint4* PQ = (const uint4*)g_PQh;
    uint4 pv[4], qv[4];
#pragma unroll
    for (int j = 0; j < 4; j++) {
        pv[j] = PQ[(size_t)sidx[j] * 32 + sub];
        qv[j] = PQ[(size_t)didx[j] * 32 + 16 + sub];
    }

    float4 w0 = ((const float4*)W_a2)[sub * 2];
    float4 w1 = ((const float4*)W_a2)[sub * 2 + 1];
    float wv[8] = {w0.x, w0.y, w0.z, w0.w, w1.x, w1.y, w1.z, w1.w};

    const __half2 slope = __float2half2_rn(0.01f);

    float acc[4] = {0.f, 0.f, 0.f, 0.f};
#pragma unroll
    for (int j = 0; j < 4; j++) {
        const __half2* ph = (const __half2*)&pv[j];
        const __half2* qh = (const __half2*)&qv[j];
#pragma unroll
        for (int i = 0; i < 4; i++) {
            __half2 x = __hadd2(ph[i], qh[i]);
            x = __hmax2(x, __hmul2(x, slope));
            float2 f = __half22float2(x);
            acc[j] = fmaf(f.x, wv[2 * i],     acc[j]);
            acc[j] = fmaf(f.y, wv[2 * i + 1], acc[j]);
        }
    }
#pragma unroll
    for (int off = 8; off; off >>= 1) {
#pragma unroll
        for (int j = 0; j < 4; j++)
            acc[j] += __shfl_xor_sync(0xFFFFFFFFu, acc[j], off);
    }

    if (sub == 0) {
        float b2 = b_a2[0];
#pragma unroll
        for (int j = 0; j < 4; j++)
            if (vv[j]) out[ee[j]] = acc[j] + b2;
    }
}

// ---------------------------------------------------------------------------
extern "C" void kernel_launch(void* const* d_in, const int* in_sizes, int n_in,
                              void* d_out, int out_size) {
    const float* node_feat = (const float*)d_in[0];
    const int*   src       = (const int*)  d_in[2];
    const int*   dst       = (const int*)  d_in[3];
    const float* W_node    = (const float*)d_in[4];
    const float* b_node    = (const float*)d_in[5];
    const float* W_a1      = (const float*)d_in[8];
    const float* b_a1      = (const float*)d_in[9];
    const float* W_a2      = (const float*)d_in[10];
    const float* b_a2      = (const float*)d_in[11];
    float* out = (float*)d_out;

    int E = in_sizes[2];
    int K = in_sizes[4] / CH;        // 118
    int M = in_sizes[0] / K;         // 10000

    {
        dim3 g((K + 1 + 31) / 32, 16);
        build_wc_kernel<<<g, 256>>>(W_node, b_node, W_a1, b_a1, K);
    }
    {
        dim3 g((M + 127) / 128, 2);
        sgemm_tc_kernel<<<g, 256>>>(node_feat, M, K);
    }
    {
        int nwarps = (E + 7) / 8;               // 8 edges per warp
        int blocks = (nwarps * 32 + 255) / 256;
        edge_kernel<<<blocks, 256>>>(src, dst, W_a2, b_a2, out, E);
    }
}